// round 4
// baseline (speedup 1.0000x reference)
#include <cuda_runtime.h>
#include <cuda_bf16.h>
#include <cstdint>

// ---------------------------------------------------------------------------
// Fully fused PatchTransformer: one block owns a 60x8 pixel tile of one
// channel. It computes the exact 7x7 reflect-pad medians for its tile
// (column-sort + row-sort + doubly-sorted band selection, all in smem/regs),
// then streams all 224 (b,f) slabs: out = clip(p*c + br + 0.1*noise).
// Medians never touch global memory.
// ---------------------------------------------------------------------------

#define PATCH 300
#define CH 3
#define BF_TOTAL 224                    // 16*14
#define PLANE (PATCH * PATCH)           // 90000
#define CHW (CH * PLANE)                // 270000
#define CHW4 (CHW / 4)                  // 67500

#define TBW 60         // output tile width  (5 exact x-tiles, 60 % 4 == 0)
#define TBH 8          // output tile height (38 y-tiles, last has 4 rows)
#define TILE_W (TBW + 6)   // 66
#define TILE_H (TBH + 6)   // 14
#define TPITCH 68
#define NCOL (TILE_W * TBH)   // 528 column windows
#define NPX (TBW * TBH)       // 480
#define NF4R (TBW / 4)        // 15 float4 per row
#define NF4 (NF4R * TBH)      // 120 float4 per tile

// compare-exchange: a <- min, b <- max
__device__ __forceinline__ void s2(float& a, float& b) {
    float t = fminf(a, b);
    b = fmaxf(a, b);
    a = t;
}

// Bring min of a[0..N-1] to a[0] and max to a[N-1]; multiset preserved.
template <int N>
__device__ __forceinline__ void mnmx(float* a) {
#pragma unroll
    for (int i = 0; i < N / 2; i++) s2(a[i], a[N - 1 - i]);
#pragma unroll
    for (int i = 1; i < (N + 1) / 2; i++) s2(a[0], a[i]);
#pragma unroll
    for (int i = N - 2; i >= N / 2; i--) s2(a[i], a[N - 1]);
}

// Exact 7-sorter (pruned Batcher-8), 16 compare-exchanges.
__device__ __forceinline__ void sort7(float* a) {
    s2(a[0], a[1]); s2(a[2], a[3]); s2(a[4], a[5]);
    s2(a[0], a[2]); s2(a[1], a[3]); s2(a[4], a[6]);
    s2(a[1], a[2]); s2(a[5], a[6]);
    s2(a[0], a[4]); s2(a[1], a[5]); s2(a[2], a[6]);
    s2(a[2], a[4]); s2(a[3], a[5]);
    s2(a[1], a[2]); s2(a[3], a[4]); s2(a[5], a[6]);
}

__device__ __forceinline__ int reflect_idx(int t) {
    t = (t < 0) ? -t : t;
    t = (t >= PATCH) ? (2 * PATCH - 2 - t) : t;
    return t;
}

struct __align__(16) Smem {
    float pmed[TBH][TBW];        // medians (16B-aligned rows: 240B stride)
    float c_s[BF_TOTAL];
    float b_s[BF_TOTAL];
    float tile[TILE_H][TPITCH];
    float scol[NCOL][7];         // sorted column windows (7-float stride:
                                 // 28B/lane -> conflict-free LDS)
};

__global__ __launch_bounds__(256)
void fused_kernel(const float* __restrict__ adv,
                  const float4* __restrict__ noise,
                  const float* __restrict__ contrast,
                  const float* __restrict__ brightness,
                  float4* __restrict__ out) {
    __shared__ Smem sm;

    const int c  = blockIdx.z;
    const int x0 = blockIdx.x * TBW;
    const int y0 = blockIdx.y * TBH;
    const int tid = threadIdx.x;
    const float* src = adv + c * PLANE;

    // ---- phase 0: load contrast/brightness + raw tile (reflect pad) ----
    if (tid < BF_TOTAL) {
        sm.c_s[tid] = contrast[tid];
        sm.b_s[tid] = brightness[tid];
    }
#pragma unroll
    for (int i = tid; i < TILE_W * TILE_H; i += 256) {
        const int lx = i % TILE_W;
        const int ly = i / TILE_W;
        const int gx = reflect_idx(x0 - 3 + lx);
        const int gy = reflect_idx(y0 - 3 + ly);
        sm.tile[ly][lx] = src[gy * PATCH + gx];
    }
    __syncthreads();

    // ---- phase A: sort all 7-tall column windows ----
    for (int t = tid; t < NCOL; t += 256) {
        const int yw  = t / TILE_W;
        const int col = t - yw * TILE_W;
        float a[7];
#pragma unroll
        for (int r = 0; r < 7; r++) a[r] = sm.tile[yw + r][col];
        sort7(a);
#pragma unroll
        for (int k = 0; k < 7; k++) sm.scol[t][k] = a[k];
    }
    __syncthreads();

    // ---- phase B: per-pixel exact median via doubly-sorted band ----
    for (int p = tid; p < NPX; p += 256) {
        const int yy = p / TBW;
        const int xx = p - yy * TBW;
        if (y0 + yy >= PATCH) continue;

        const int base = yy * TILE_W + xx;
        float S[16];
        float r[7];

#define LOAD_SORT_ROW(I)                                           \
        do {                                                       \
            _Pragma("unroll")                                      \
            for (int dx = 0; dx < 7; dx++) r[dx] = sm.scol[base + dx][I]; \
            sort7(r);                                              \
        } while (0)

        LOAD_SORT_ROW(2);
        S[0] = r[2]; S[1] = r[3]; S[2] = r[4]; S[3] = r[5]; S[4] = r[6];
        LOAD_SORT_ROW(3);
        S[5] = r[1]; S[6] = r[2]; S[7] = r[3]; S[8] = r[4]; S[9] = r[5];
        LOAD_SORT_ROW(4);
        S[10] = r[0]; S[11] = r[1]; S[12] = r[2]; S[13] = r[3]; S[14] = r[4];
        LOAD_SORT_ROW(1);
        S[15] = r[3];
        float f0 = r[4], f1 = r[5], f2 = r[6];

        mnmx<16>(S); S[0] = f0; S[15] = f1;
        LOAD_SORT_ROW(5);
        mnmx<16>(S); S[0] = f2;   S[15] = r[0];
        mnmx<16>(S); S[0] = r[1]; S[15] = r[2];
        float f3 = r[3];
        LOAD_SORT_ROW(0);
        mnmx<16>(S); S[0] = f3;   S[15] = r[4];
        mnmx<16>(S); S[0] = r[5]; S[15] = r[6];
        LOAD_SORT_ROW(6);
        mnmx<16>(S); S[0] = r[0]; S[15] = r[1];
        mnmx<16>(S); S[0] = r[2];        // live: S[0..14], rank 7

        mnmx<15>(S);
        mnmx<13>(S + 1);
        mnmx<11>(S + 2);
        mnmx<9>(S + 3);
        mnmx<7>(S + 4);
        mnmx<5>(S + 5);
        s2(S[6], S[7]); s2(S[7], S[8]); s2(S[6], S[7]);

        sm.pmed[yy][xx] = S[7];
#undef LOAD_SORT_ROW
    }
    __syncthreads();

    // ---- phase C: stream all 224 slabs with medians in registers ----
    if (tid >= 240) return;
    const int f4  = tid % NF4;           // 0..119
    const int sl0 = tid / NF4;           // 0 or 1
    const int rr  = f4 / NF4R;           // row 0..7
    const int xq  = f4 - rr * NF4R;      // 0..14
    const int oy  = y0 + rr;
    if (oy >= PATCH) return;

    const float4 p4 = *reinterpret_cast<const float4*>(&sm.pmed[rr][xq * 4]);
    const unsigned g0 = (unsigned)(c * PLANE + oy * PATCH + x0 + xq * 4) >> 2;

#pragma unroll 4
    for (int sl = sl0; sl < BF_TOTAL; sl += 2) {
        const unsigned idx = g0 + (unsigned)sl * CHW4;
        const float4 n = __ldcs(noise + idx);
        const float cc = sm.c_s[sl];
        const float bb = sm.b_s[sl];
        float4 o;
        o.x = fminf(fmaxf(fmaf(n.x, 0.1f, fmaf(p4.x, cc, bb)), 1e-6f), 0.99999f);
        o.y = fminf(fmaxf(fmaf(n.y, 0.1f, fmaf(p4.y, cc, bb)), 1e-6f), 0.99999f);
        o.z = fminf(fmaxf(fmaf(n.z, 0.1f, fmaf(p4.z, cc, bb)), 1e-6f), 0.99999f);
        o.w = fminf(fmaxf(fmaf(n.w, 0.1f, fmaf(p4.w, cc, bb)), 1e-6f), 0.99999f);
        __stcs(out + idx, o);
    }
}

// ---------------------------------------------------------------------------
// Inputs (metadata order):
//   0: adv_patch  [3,300,300] f32
//   1: lab_batch  [16,14,5]   f32 (unused)
//   2: contrast   [16,14]     f32
//   3: brightness [16,14]     f32
//   4: noise      [16,14,3,300,300] f32
//   5: img_size   scalar (unused)
// Output: [16,14,3,300,300] f32
// ---------------------------------------------------------------------------
extern "C" void kernel_launch(void* const* d_in, const int* in_sizes, int n_in,
                              void* d_out, int out_size) {
    const float* adv_patch  = (const float*)d_in[0];
    const float* contrast   = (const float*)d_in[2];
    const float* brightness = (const float*)d_in[3];
    const float* noise      = (const float*)d_in[4];
    float* out = (float*)d_out;

    dim3 grid(PATCH / TBW, (PATCH + TBH - 1) / TBH, CH);   // 5 x 38 x 3 = 570
    fused_kernel<<<grid, 256>>>(adv_patch, (const float4*)noise,
                                contrast, brightness, (float4*)out);
}

// round 5
// speedup vs baseline: 1.2434x; 1.2434x over previous
#include <cuda_runtime.h>
#include <cuda_bf16.h>
#include <cstdint>

// ---------------------------------------------------------------------------
// PatchTransformer, channel-pipelined two-phase:
//   med(c):   exact 7x7 median (reflect) of channel c  -> g_p[c]
//   apply(c): out = clip(p*contrast + brightness + 0.1*noise) for channel c
// med(c+1) overlaps apply(c) via a forked side stream (graph-capturable
// event fork/join). Apply keeps the proven flat linear-indexed shape.
// ---------------------------------------------------------------------------

#define PATCH 300
#define CH 3
#define BF_TOTAL 224                    // 16*14
#define PLANE (PATCH * PATCH)           // 90000
#define PLANE4 (PLANE / 4)              // 22500
#define CHW (CH * PLANE)                // 270000
#define CHW4 (CHW / 4)                  // 67500

__device__ float g_p[CHW];

// compare-exchange: a <- min, b <- max
__device__ __forceinline__ void s2(float& a, float& b) {
    float t = fminf(a, b);
    b = fmaxf(a, b);
    a = t;
}

template <int N>
__device__ __forceinline__ void mnmx(float* a) {
#pragma unroll
    for (int i = 0; i < N / 2; i++) s2(a[i], a[N - 1 - i]);
#pragma unroll
    for (int i = 1; i < (N + 1) / 2; i++) s2(a[0], a[i]);
#pragma unroll
    for (int i = N - 2; i >= N / 2; i--) s2(a[i], a[N - 1]);
}

// Exact 7-sorter (pruned Batcher-8), 16 compare-exchanges.
__device__ __forceinline__ void sort7(float* a) {
    s2(a[0], a[1]); s2(a[2], a[3]); s2(a[4], a[5]);
    s2(a[0], a[2]); s2(a[1], a[3]); s2(a[4], a[6]);
    s2(a[1], a[2]); s2(a[5], a[6]);
    s2(a[0], a[4]); s2(a[1], a[5]); s2(a[2], a[6]);
    s2(a[2], a[4]); s2(a[3], a[5]);
    s2(a[1], a[2]); s2(a[3], a[4]); s2(a[5], a[6]);
}

__device__ __forceinline__ int reflect_idx(int t) {
    t = (t < 0) ? -t : t;
    t = (t >= PATCH) ? (2 * PATCH - 2 - t) : t;
    return t;
}

// Tile: 32x8 outputs per block, halo 3 -> 38x14 raw tile.
#define TBX 32
#define TBY 8
#define TILE_W (TBX + 6)   // 38
#define TILE_H (TBY + 6)   // 14
#define TILE_PITCH 40
#define NCOLTASK (TBY * TILE_W)   // 304

__global__ __launch_bounds__(TBX * TBY)
void median7_kernel(const float* __restrict__ src_all, int c) {
    __shared__ float tile[TILE_H][TILE_PITCH];
    __shared__ float scol[NCOLTASK][7];

    const int x0 = blockIdx.x * TBX;
    const int y0 = blockIdx.y * TBY;
    const float* s = src_all + c * PLANE;

    const int tx  = threadIdx.x;
    const int ty  = threadIdx.y;
    const int tid = ty * TBX + tx;

#pragma unroll
    for (int i = tid; i < TILE_W * TILE_H; i += TBX * TBY) {
        const int lx = i % TILE_W;
        const int ly = i / TILE_W;
        const int gx = reflect_idx(x0 - 3 + lx);
        const int gy = reflect_idx(y0 - 3 + ly);
        tile[ly][lx] = s[gy * PATCH + gx];
    }
    __syncthreads();

    // phase A: sort all 7-tall column windows (shared across x-neighbors)
    for (int t = tid; t < NCOLTASK; t += TBX * TBY) {
        const int yw  = t / TILE_W;
        const int col = t - yw * TILE_W;
        float a[7];
#pragma unroll
        for (int r = 0; r < 7; r++) a[r] = tile[yw + r][col];
        sort7(a);
#pragma unroll
        for (int k = 0; k < 7; k++) scol[t][k] = a[k];
    }
    __syncthreads();

    const int ox = x0 + tx;
    const int oy = y0 + ty;
    if (ox >= PATCH || oy >= PATCH) return;

    // phase B: row sort + doubly-sorted 29-candidate band selection
    const int base = ty * TILE_W + tx;
    float S[16];
    float r[7];

#define LOAD_SORT_ROW(I)                                           \
    do {                                                           \
        _Pragma("unroll")                                          \
        for (int dx = 0; dx < 7; dx++) r[dx] = scol[base + dx][I]; \
        sort7(r);                                                  \
    } while (0)

    LOAD_SORT_ROW(2);
    S[0] = r[2]; S[1] = r[3]; S[2] = r[4]; S[3] = r[5]; S[4] = r[6];
    LOAD_SORT_ROW(3);
    S[5] = r[1]; S[6] = r[2]; S[7] = r[3]; S[8] = r[4]; S[9] = r[5];
    LOAD_SORT_ROW(4);
    S[10] = r[0]; S[11] = r[1]; S[12] = r[2]; S[13] = r[3]; S[14] = r[4];
    LOAD_SORT_ROW(1);
    S[15] = r[3];
    float f0 = r[4], f1 = r[5], f2 = r[6];

    mnmx<16>(S); S[0] = f0; S[15] = f1;
    LOAD_SORT_ROW(5);
    mnmx<16>(S); S[0] = f2;   S[15] = r[0];
    mnmx<16>(S); S[0] = r[1]; S[15] = r[2];
    float f3 = r[3];
    LOAD_SORT_ROW(0);
    mnmx<16>(S); S[0] = f3;   S[15] = r[4];
    mnmx<16>(S); S[0] = r[5]; S[15] = r[6];
    LOAD_SORT_ROW(6);
    mnmx<16>(S); S[0] = r[0]; S[15] = r[1];
    mnmx<16>(S); S[0] = r[2];          // live: S[0..14], rank 7

    mnmx<15>(S);
    mnmx<13>(S + 1);
    mnmx<11>(S + 2);
    mnmx<9>(S + 3);
    mnmx<7>(S + 4);
    mnmx<5>(S + 5);
    s2(S[6], S[7]); s2(S[7], S[8]); s2(S[6], S[7]);

    g_p[c * PLANE + oy * PATCH + ox] = S[7];
#undef LOAD_SORT_ROW
}

// ---------------------------------------------------------------------------
// Per-channel apply: flat over (slab, rem4-within-channel), 2 float4/thread.
// Pairs never straddle a slab boundary (PLANE4 = 22500 is even).
// ---------------------------------------------------------------------------
#define CH_TOTAL4 (BF_TOTAL * PLANE4)   // 5,040,000 float4 per channel
#define CH_HALF4  (CH_TOTAL4 / 2)       // 2,520,000

__global__ __launch_bounds__(256)
void apply_kernel(const float4* __restrict__ noise,
                  const float* __restrict__ contrast,
                  const float* __restrict__ brightness,
                  float4* __restrict__ out,
                  int c) {
    const unsigned gtid = blockIdx.x * 256u + threadIdx.x;
    if (gtid >= CH_HALF4) return;

    const unsigned i   = gtid * 2u;                  // pair index in channel
    const unsigned sl  = i / (unsigned)PLANE4;
    const unsigned rem = i - sl * (unsigned)PLANE4;  // even
    const unsigned idx = sl * (unsigned)CHW4 + (unsigned)c * PLANE4 + rem;

    const float4* gp4 = reinterpret_cast<const float4*>(g_p) + c * PLANE4;
    const float4 n0 = __ldcs(noise + idx);
    const float4 n1 = __ldcs(noise + idx + 1);
    const float4 p0 = __ldg(gp4 + rem);
    const float4 p1 = __ldg(gp4 + rem + 1);
    const float cc = __ldg(&contrast[sl]);
    const float bb = __ldg(&brightness[sl]);

    float4 r0, r1;
    r0.x = fminf(fmaxf(fmaf(n0.x, 0.1f, fmaf(p0.x, cc, bb)), 1e-6f), 0.99999f);
    r0.y = fminf(fmaxf(fmaf(n0.y, 0.1f, fmaf(p0.y, cc, bb)), 1e-6f), 0.99999f);
    r0.z = fminf(fmaxf(fmaf(n0.z, 0.1f, fmaf(p0.z, cc, bb)), 1e-6f), 0.99999f);
    r0.w = fminf(fmaxf(fmaf(n0.w, 0.1f, fmaf(p0.w, cc, bb)), 1e-6f), 0.99999f);
    r1.x = fminf(fmaxf(fmaf(n1.x, 0.1f, fmaf(p1.x, cc, bb)), 1e-6f), 0.99999f);
    r1.y = fminf(fmaxf(fmaf(n1.y, 0.1f, fmaf(p1.y, cc, bb)), 1e-6f), 0.99999f);
    r1.z = fminf(fmaxf(fmaf(n1.z, 0.1f, fmaf(p1.z, cc, bb)), 1e-6f), 0.99999f);
    r1.w = fminf(fmaxf(fmaf(n1.w, 0.1f, fmaf(p1.w, cc, bb)), 1e-6f), 0.99999f);

    __stcs(out + idx,     r0);
    __stcs(out + idx + 1, r1);
}

// ---------------------------------------------------------------------------
// Inputs (metadata order):
//   0: adv_patch  [3,300,300] f32
//   1: lab_batch  [16,14,5]   f32 (unused)
//   2: contrast   [16,14]     f32
//   3: brightness [16,14]     f32
//   4: noise      [16,14,3,300,300] f32
//   5: img_size   scalar (unused)
// Output: [16,14,3,300,300] f32
// ---------------------------------------------------------------------------
extern "C" void kernel_launch(void* const* d_in, const int* in_sizes, int n_in,
                              void* d_out, int out_size) {
    const float* adv_patch  = (const float*)d_in[0];
    const float* contrast   = (const float*)d_in[2];
    const float* brightness = (const float*)d_in[3];
    const float* noise      = (const float*)d_in[4];
    float* out = (float*)d_out;

    cudaStream_t t;
    cudaStreamCreateWithFlags(&t, cudaStreamNonBlocking);
    cudaEvent_t ev[CH], ej;
    for (int c = 0; c < CH; c++) cudaEventCreateWithFlags(&ev[c], cudaEventDisableTiming);
    cudaEventCreateWithFlags(&ej, cudaEventDisableTiming);

    dim3 mblk(TBX, TBY, 1);
    dim3 mgrd((PATCH + TBX - 1) / TBX, (PATCH + TBY - 1) / TBY, 1);
    const int ablocks = (CH_HALF4 + 255) / 256;

    for (int c = 0; c < CH; c++) {
        median7_kernel<<<mgrd, mblk>>>(adv_patch, c);   // capture/default stream
        cudaEventRecord(ev[c], 0);
    }
    for (int c = 0; c < CH; c++) {
        cudaStreamWaitEvent(t, ev[c], 0);
        apply_kernel<<<ablocks, 256, 0, t>>>((const float4*)noise, contrast,
                                             brightness, (float4*)out, c);
    }
    cudaEventRecord(ej, t);
    cudaStreamWaitEvent(0, ej, 0);      // join side stream back

    for (int c = 0; c < CH; c++) cudaEventDestroy(ev[c]);
    cudaEventDestroy(ej);
    cudaStreamDestroy(t);
}